// round 1
// baseline (speedup 1.0000x reference)
#include <cuda_runtime.h>
#include <cuda_bf16.h>

// CTC forward (negative log-likelihood), matching keras ctc_batch_cost.
// B=128, T=1024, V=512, L=128, S=2L+1=257, blank = V-1.
//
// Design:
//  - 1 CTA per batch element (grid = 128).
//  - 288 threads (9 warps):
//      warps 0-3  (tid   0..127): odd  elements s=2*tid+1   (3-term recursion)
//      warps 4-7  (tid 128..255): even elements s=2*(tid-128) (2-term recursion)
//      warp  8    (tid 256)     : even element  s=256
//    Odd/even split by warp balances MUFU (exp/log) load across SMSPs.
//  - alpha double-buffered in shared -> ONE __syncthreads per time step.
//  - 8-deep per-thread register prefetch of the gathered probability
//    Y[b][t][cls] (cls = label for odd threads, blank for even threads).
//  - log-domain recursion with fused log:  new = m + logf(sum * (p+EPS)),
//    sum = 1 + exp(lo-m) (+ exp(x-m)), exploiting that exp(max-m)=1.

#define NEGV (-1e30f)
#define EPSV (1e-7f)

constexpr int Bc = 128;
constexpr int Tc = 1024;
constexpr int Vc = 512;
constexpr int Lc = 128;
constexpr int Sc = 257;     // 2L+1
constexpr int PF = 8;       // prefetch depth
constexpr int NT = 288;     // 9 warps

__global__ __launch_bounds__(NT, 1)
void ctc_forward_kernel(const int*   __restrict__ labels,     // [B, L]
                        const int*   __restrict__ lab_len,    // [B, 1]
                        const float* __restrict__ Y,          // [B, T, V] softmax probs
                        const int*   __restrict__ in_len,     // [B, 1]
                        float*       __restrict__ out)        // [B, 1]
{
    __shared__ float As[2][Sc + 7];   // double-buffered alpha, padded
    __shared__ int   lab_sh[Lc];

    const int b   = blockIdx.x;
    const int tid = threadIdx.x;

    if (tid < Lc) lab_sh[tid] = labels[b * Lc + tid];
    const int len = in_len[b];

    // ---- thread role ----
    int  s = -1;
    bool isOdd = false;
    if (tid < 128)          { s = 2 * tid + 1;        isOdd = true;  }
    else if (tid < 256)     { s = 2 * (tid - 128);                   }
    else if (tid == 256)    { s = 256;                               }

    // init alpha0
    float a = NEGV;
    if (s >= 0) {
        a = (s == 0) ? 0.0f : NEGV;
        As[0][s] = a;
    }
    __syncthreads();   // labels + alpha0 visible

    int  cls = Vc - 1;   // blank for even threads
    bool cs  = false;    // can_skip (odd threads only)
    if (isOdd) {
        const int l     = tid;
        const int mycls = lab_sh[l];
        cls = mycls;
        cs  = (l > 0) && (mycls != (Vc - 1)) && (mycls != lab_sh[l - 1]);
    }

    // ---- prefetch pipeline ----
    const float* __restrict__ Yb = Y + (size_t)b * Tc * Vc;
    float pbuf[PF];
    if (s >= 0) {
        #pragma unroll
        for (int j = 0; j < PF; j++) {
            int tp = j;
            if (tp > len - 1) tp = len - 1;
            if (tp < 0) tp = 0;
            pbuf[j] = Yb[tp * Vc + cls];
        }
    }

    // ---- main recursion over time ----
    int rd = 0;
    for (int tb = 0; tb < len; tb += PF) {
        #pragma unroll
        for (int j = 0; j < PF; j++) {
            const int t = tb + j;
            if (t >= len) break;              // uniform across block
            if (s >= 0) {
                const float p = pbuf[j] + EPSV;
                // issue next prefetch early
                int tp = t + PF;
                if (tp > len - 1) tp = len - 1;
                pbuf[j] = Yb[tp * Vc + cls];

                const float a1 = (s > 0) ? As[rd][s - 1] : NEGV;
                float nv;
                if (isOdd) {
                    const float a2 = cs ? As[rd][s - 2] : NEGV;
                    const float lo = fminf(a, a1);
                    const float hi = fmaxf(a, a1);
                    const float m  = fmaxf(hi, a2);
                    const float x  = fminf(hi, a2);
                    const float sum = 1.0f + __expf(lo - m) + __expf(x - m);
                    nv = m + __logf(sum * p);
                } else {
                    const float m  = fmaxf(a, a1);
                    const float lo = fminf(a, a1);
                    const float sum = 1.0f + __expf(lo - m);
                    nv = m + __logf(sum * p);
                }
                a = nv;
                As[rd ^ 1][s] = nv;
            }
            __syncthreads();
            rd ^= 1;
        }
    }

    // ---- final reduction: loss = -logaddexp(alpha[2*lab], alpha[2*lab-1]) ----
    if (tid == 0) {
        const int   ll = lab_len[b];
        const float aL = As[rd][2 * ll];
        const float aP = As[rd][2 * ll - 1];
        const float m  = fmaxf(aL, aP);
        const float lo = fminf(aL, aP);
        out[b] = -(m + __logf(1.0f + __expf(lo - m)));
    }
}

extern "C" void kernel_launch(void* const* d_in, const int* in_sizes, int n_in,
                              void* d_out, int out_size) {
    const int*   labels  = (const int*)d_in[0];   // true_labels [B, L]
    const int*   lab_len = (const int*)d_in[1];   // true_lengths [B, 1]
    const float* Y       = (const float*)d_in[2]; // predicted_labels [B, T, V]
    const int*   in_len  = (const int*)d_in[3];   // predicted_lengths [B, 1]
    float*       out     = (float*)d_out;         // [B, 1]

    ctc_forward_kernel<<<Bc, NT>>>(labels, lab_len, Y, in_len, out);
}

// round 5
// speedup vs baseline: 2.9772x; 2.9772x over previous
#include <cuda_runtime.h>
#include <cuda_bf16.h>
#include <cstdint>

// CTC forward negative log-likelihood (keras ctc_batch_cost semantics).
// B=128, T=1024, V=512, L=128, S=2L+1=257, blank=V-1.
//
// Design:
//  - 1 CTA per batch element (grid=128), 288 threads (9 warps):
//      tid   0..127 : odd states  s=2*tid+1 (3-term recursion)  [also cp.async producers]
//      tid 128..255 : even states s=2*(tid-128) (2-term)
//      tid 256      : even state  s=256
//  - Per time step, the full 2KB probability row Y[b][t][:] is staged into an
//    8-deep shared ring via coalesced cp.async.cg (128 threads x 16B), replacing
//    ~225 scattered-L1tex wavefronts/step with 16 coalesced ones.
//  - ONE __syncthreads per step publishes both alpha (double-buffered) and the
//    next staged row. Ring slot t%D is overwritten only after the barrier that
//    closes step t (all readers done).
//  - Recursion runs in log2 domain: logaddexp2 via raw ex2/lg2.approx MUFU,
//    fused  nv = m + lg2(sum * (p+EPS));  final result scaled by ln2.

#define NEGV (-1e30f)
#define EPSV (1e-7f)
#define LN2F (0.6931471805599453f)

constexpr int Bc = 128;
constexpr int Tc = 1024;
constexpr int Vc = 512;
constexpr int Lc = 128;
constexpr int Sc = 257;     // 2L+1
constexpr int D  = 8;       // ring stages
constexpr int NT = 288;     // 9 warps

__device__ __forceinline__ float ex2f(float x) {
    float r; asm("ex2.approx.f32 %0, %1;" : "=f"(r) : "f"(x)); return r;
}
__device__ __forceinline__ float lg2f(float x) {
    float r; asm("lg2.approx.f32 %0, %1;" : "=f"(r) : "f"(x)); return r;
}
__device__ __forceinline__ void cp_async16(uint32_t saddr, const void* gptr) {
    asm volatile("cp.async.cg.shared.global [%0], [%1], 16;" :: "r"(saddr), "l"(gptr));
}
__device__ __forceinline__ void cp_commit() {
    asm volatile("cp.async.commit_group;");
}
template<int N>
__device__ __forceinline__ void cp_wait() {
    asm volatile("cp.async.wait_group %0;" :: "n"(N));
}

__global__ __launch_bounds__(NT, 1)
void ctc_forward_kernel(const int*   __restrict__ labels,     // [B, L]
                        const int*   __restrict__ lab_len,    // [B, 1]
                        const float* __restrict__ Y,          // [B, T, V]
                        const int*   __restrict__ in_len,     // [B, 1]
                        float*       __restrict__ out)        // [B, 1]
{
    __shared__ float rows[D][Vc];      // staged probability rows (16KB)
    __shared__ float As[2][Sc + 7];    // double-buffered alpha (log2 domain)
    __shared__ int   lab_sh[Lc];

    const int b   = blockIdx.x;
    const int tid = threadIdx.x;

    if (tid < Lc) lab_sh[tid] = labels[b * Lc + tid];
    const int len = in_len[b];

    // ---- thread role ----
    int  s = -1;
    bool isOdd = false;
    if (tid < 128)       { s = 2 * tid + 1;         isOdd = true; }
    else if (tid < 256)  { s = 2 * (tid - 128);                   }
    else if (tid == 256) { s = 256;                               }

    float a = NEGV;
    if (s >= 0) {
        a = (s == 0) ? 0.0f : NEGV;   // log2(1) = 0
        As[0][s] = a;
    }

    const float* __restrict__ Yb = Y + (size_t)b * Tc * Vc;
    const bool producer = (tid < 128);

    // ---- prologue: stage rows 0..D-1 (one commit group per row) ----
    if (producer) {
        #pragma unroll
        for (int j = 0; j < D; j++) {
            uint32_t sa = (uint32_t)__cvta_generic_to_shared(&rows[j][tid * 4]);
            int tr = (j < len) ? j : (len > 0 ? len - 1 : 0);
            cp_async16(sa, Yb + (size_t)tr * Vc + tid * 4);
            cp_commit();
        }
        cp_wait<D - 1>();             // row 0 complete
    }
    __syncthreads();                  // labels, alpha0, row 0 visible

    int  cls = Vc - 1;                // blank for even threads
    bool cs  = false;
    if (isOdd) {
        const int mycls = lab_sh[tid];
        cls = mycls;
        cs  = (tid > 0) && (mycls != (Vc - 1)) && (mycls != lab_sh[tid - 1]);
    }

    // ---- main recursion ----
    int rd = 0;
    for (int t = 0; t < len; ++t) {
        const int stg = t & (D - 1);

        if (s >= 0) {
            const float p  = rows[stg][cls] + EPSV;
            const float a1 = (s > 0) ? As[rd][s - 1] : NEGV;
            float nv;
            if (isOdd) {
                const float a2 = cs ? As[rd][s - 2] : NEGV;
                const float hi = fmaxf(a, a1);
                const float lo = fminf(a, a1);
                const float m  = fmaxf(hi, a2);
                const float x  = fminf(hi, a2);
                const float sum = 1.0f + ex2f(lo - m) + ex2f(x - m);
                nv = m + lg2f(sum * p);
            } else {
                const float m  = fmaxf(a, a1);
                const float lo = fminf(a, a1);
                const float sum = 1.0f + ex2f(lo - m);
                nv = m + lg2f(sum * p);
            }
            a = nv;
            As[rd ^ 1][s] = nv;
        }

        if (producer) cp_wait<D - 2>();   // row t+1 complete (issued >= D-1 steps ago)
        __syncthreads();                  // publish alpha_t and row t+1
        if (producer && (t + D) < len) {  // safe to overwrite slot t%D now
            cp_async16((uint32_t)__cvta_generic_to_shared(&rows[stg][tid * 4]),
                       Yb + (size_t)(t + D) * Vc + tid * 4);
            cp_commit();
        }
        rd ^= 1;
    }

    // ---- final: loss = -ln2 * logaddexp2(alpha[2*lab], alpha[2*lab-1]) ----
    if (tid == 0) {
        const int   ll = lab_len[b];
        const float aL = As[rd][2 * ll];
        const float aP = As[rd][2 * ll - 1];
        const float m  = fmaxf(aL, aP);
        const float lo = fminf(aL, aP);
        out[b] = -LN2F * (m + lg2f(1.0f + ex2f(lo - m)));
    }
}

extern "C" void kernel_launch(void* const* d_in, const int* in_sizes, int n_in,
                              void* d_out, int out_size) {
    const int*   labels  = (const int*)d_in[0];   // true_labels [B, L]
    const int*   lab_len = (const int*)d_in[1];   // true_lengths [B, 1]
    const float* Y       = (const float*)d_in[2]; // predicted_labels [B, T, V]
    const int*   in_len  = (const int*)d_in[3];   // predicted_lengths [B, 1]
    float*       out     = (float*)d_out;         // [B, 1]

    ctc_forward_kernel<<<Bc, NT>>>(labels, lab_len, Y, in_len, out);
}